// round 11
// baseline (speedup 1.0000x reference)
#include <cuda_runtime.h>
#include <cuda_bf16.h>
#include <cstdint>

#define LV       4087
#define BROWS    2048
#define NSTEP    1021
#define NCH      4096
#define EPSF     1e-6f
#define RSTRIDE  2048
#define PADSTEP  1024

typedef unsigned long long ull;

// Packed coefficient scratch: per (step, row) -> {xP,xT,yP,yT} + {zP,zT}
__device__ float4 g_pk0[(size_t)PADSTEP * RSTRIDE];   // 64MB
__device__ float2 g_pk1[(size_t)PADSTEP * RSTRIDE];   // 32MB
__device__ float4 g_init[NCH];   // {l1, -l2*ct0, l2*st0, 0} per chain
__device__ double g_acc;
__device__ unsigned g_count;

__device__ __forceinline__ float dnbl(float v) { return ((v + 1.0f) * 0.5f) * 2.1f + 0.9f; }
__device__ __forceinline__ float dnd (float v) { return ((v + 1.0f) * 0.5f) * 3.5f + 1.5f; }
__device__ __forceinline__ float clip1(float v) { return fminf(fmaxf(v, -1.0f), 1.0f); }

__device__ __forceinline__ float rsq_approx(float x) {
    float y; asm("rsqrt.approx.f32 %0, %1;" : "=f"(y) : "f"(x)); return y;
}

// ---- f32x2 packed helpers (sm_103a FFMA2/FMUL2/FADD2 via PTX) ----
__device__ __forceinline__ ull f2mul(ull a, ull b) {
    ull r; asm("mul.rn.f32x2 %0, %1, %2;" : "=l"(r) : "l"(a), "l"(b)); return r;
}
__device__ __forceinline__ ull f2add(ull a, ull b) {
    ull r; asm("add.rn.f32x2 %0, %1, %2;" : "=l"(r) : "l"(a), "l"(b)); return r;
}
__device__ __forceinline__ ull f2fma(ull a, ull b, ull c) {
    ull r; asm("fma.rn.f32x2 %0, %1, %2, %3;" : "=l"(r) : "l"(a), "l"(b), "l"(c)); return r;
}
__device__ __forceinline__ ull f2neg(ull a, ull sgn) {
    ull r; asm("xor.b64 %0, %1, %2;" : "=l"(r) : "l"(a), "l"(sgn)); return r;
}
__device__ __forceinline__ ull f2pack(float lo, float hi) {
    ull r; asm("mov.b64 %0, {%1, %2};" : "=l"(r) : "f"(lo), "f"(hi)); return r;
}
__device__ __forceinline__ void f2unpack(ull v, float& lo, float& hi) {
    asm("mov.b64 {%0, %1}, %2;" : "=f"(lo), "=f"(hi) : "l"(v));
}

// ---------------------------------------------------------------------------
// Prep: thread handles one (step, row) and computes BOTH pred and targ
// coefficients, writing the packed layout. Compute phase lane = step
// (coalesced reads), smem transpose, packed coalesced writes.
// ---------------------------------------------------------------------------
__device__ __forceinline__ float3 coef_one(const float* __restrict__ v, int j, bool doClip)
{
    float b1r = v[3064 + j + 1];
    float b2r = v[3064 + j + 2];
    float dr  = v[2042 + j + 1];
    float s0  = v[2 * j];
    float s1  = v[2 * j + 1];
    if (doClip) {
        b1r = clip1(b1r); b2r = clip1(b2r); dr = clip1(dr);
        s0 = clip1(s0);   s1 = clip1(s1);
    }
    float l1 = dnbl(b1r), l = dnbl(b2r), dd = dnd(dr);
    float ct = (l1 * l1 + l * l - dd * dd) / (2.0f * l1 * l);
    ct = fminf(fmaxf(ct, -1.0f + EPSF), 1.0f - EPSF);
    float st = sqrtf((1.0f - ct) * (1.0f + ct));

    float h2 = s0 * s0 + s1 * s1;
    float cch, sch;
    if (h2 < 1e-30f) { cch = 1.0f; sch = 0.0f; }
    else { float rh = rsqrtf(h2); cch = s1 * rh; sch = s0 * rh; }

    float3 o;
    o.x = -l * ct;
    o.y =  l * st * cch;
    o.z =  l * st * sch;
    return o;
}

__global__ __launch_bounds__(1024) void prep_kernel(const float* __restrict__ pred,
                                                    const float* __restrict__ targ)
{
    __shared__ float4 S0[32][33];
    __shared__ float2 S1[32][33];
    const int tx = threadIdx.x;            // step offset (compute) / row offset (write)
    const int ty = threadIdx.y;
    const int J0 = blockIdx.x * 32;
    const int R0 = blockIdx.y * 32;
    const int r  = R0 + ty;
    const int j  = J0 + tx;
    const float* __restrict__ vp = pred + (size_t)r * LV;
    const float* __restrict__ vt = targ + (size_t)r * LV;

    if (blockIdx.x == 0 && blockIdx.y == 0 && tx == 0 && ty == 0) {
        g_acc = 0.0;
        g_count = 0u;
    }

    // per-chain init (atoms 1,2 geometry), once per row
    if (blockIdx.x == 0 && tx == 0) {
        {   // pred (clipped)
            float b0 = clip1(vp[3064]), b1 = clip1(vp[3065]), dr = clip1(vp[2042]);
            float l1 = dnbl(b0), l2 = dnbl(b1), dd = dnd(dr);
            float ct = (l1 * l1 + l2 * l2 - dd * dd) / (2.0f * l1 * l2);
            ct = fminf(fmaxf(ct, -1.0f + EPSF), 1.0f - EPSF);
            float st = sqrtf((1.0f - ct) * (1.0f + ct));
            g_init[r] = make_float4(l1, -l2 * ct, l2 * st, 0.0f);
        }
        {   // targ (unclipped)
            float b0 = vt[3064], b1 = vt[3065], dr = vt[2042];
            float l1 = dnbl(b0), l2 = dnbl(b1), dd = dnd(dr);
            float ct = (l1 * l1 + l2 * l2 - dd * dd) / (2.0f * l1 * l2);
            ct = fminf(fmaxf(ct, -1.0f + EPSF), 1.0f - EPSF);
            float st = sqrtf((1.0f - ct) * (1.0f + ct));
            g_init[r + BROWS] = make_float4(l1, -l2 * ct, l2 * st, 0.0f);
        }
    }

    float3 oP = make_float3(0.f, 0.f, 0.f);
    float3 oT = make_float3(0.f, 0.f, 0.f);
    if (j < NSTEP) {
        oP = coef_one(vp, j, true);
        oT = coef_one(vt, j, false);
    }
    S0[ty][tx] = make_float4(oP.x, oT.x, oP.y, oT.y);
    S1[ty][tx] = make_float2(oP.z, oT.z);
    __syncthreads();

    int jo = J0 + ty;
    size_t idx = (size_t)jo * RSTRIDE + (R0 + tx);
    g_pk0[idx] = S0[tx][ty];
    g_pk1[idx] = S1[tx][ty];
}

// ---------------------------------------------------------------------------
// Packed scan step (R7 math, both chains per instruction).
// u1 = A (overwritten with new bond e), u2 = B. Caller alternates roles.
// ---------------------------------------------------------------------------
__device__ __forceinline__ void step_pk(
    ull cfx, ull cfy, ull cfz,
    ull& Ax, ull& Ay, ull& Az,        // u1 on entry; e on exit
    ull  Bx, ull  By, ull  Bz,        // u2
    ull& cx, ull& cy, ull& cz,
    ull NEPS, ull SGN,
    float& accx, float& accy, float& accz)
{
    // c12 = u1 x u2
    ull c12x = f2fma(Ay, Bz, f2neg(f2mul(Az, By), SGN));
    ull c12y = f2fma(Az, Bx, f2neg(f2mul(Ax, Bz), SGN));
    ull c12z = f2fma(Ax, By, f2neg(f2mul(Ay, Bx), SGN));

    // cxu = c12 x u2
    ull cxux = f2fma(c12y, Bz, f2neg(f2mul(c12z, By), SGN));
    ull cxuy = f2fma(c12z, Bx, f2neg(f2mul(c12x, Bz), SGN));
    ull cxuz = f2fma(c12x, By, f2neg(f2mul(c12y, Bx), SGN));

    ull A2 = f2fma(Bx, Bx, f2fma(By, By, f2mul(Bz, Bz)));
    ull C2 = f2fma(c12x, c12x, f2fma(c12y, c12y, f2mul(c12z, c12z)));

    float alo, ahi, clo, chi;
    f2unpack(A2, alo, ahi);
    f2unpack(C2, clo, chi);
    ull r1 = f2pack(rsq_approx(alo), rsq_approx(ahi));
    ull rC = f2pack(rsq_approx(clo), rsq_approx(chi));

    ull inv1 = f2fma(f2mul(r1, NEPS), r1, r1);        // 1/(|u2|+eps)
    ull an   = f2mul(A2, r1);                         // |u2|
    ull t    = f2mul(an, rC);
    ull rcpD = f2fma(f2mul(t, NEPS), rC, rC);         // 1/(|c12|+eps*|u2|)

    ull s1 = f2mul(cfx, inv1);
    ull s3 = f2mul(cfz, rcpD);
    ull s2 = f2mul(f2mul(cfy, inv1), rcpD);

    ull ex = f2fma(s1, Bx, f2fma(s2, cxux, f2mul(s3, c12x)));
    ull ey = f2fma(s1, By, f2fma(s2, cxuy, f2mul(s3, c12y)));
    ull ez = f2fma(s1, Bz, f2fma(s2, cxuz, f2mul(s3, c12z)));

    cx = f2add(cx, ex);
    cy = f2add(cy, ey);
    cz = f2add(cz, ez);
    Ax = ex; Ay = ey; Az = ez;                        // new u2; old B becomes u1

    // loss: diff of the two packed halves of the position
    float plo, phi;
    f2unpack(cx, plo, phi); float fx = plo - phi; accx = fmaf(fx, fx, accx);
    f2unpack(cy, plo, phi); float fy = plo - phi; accy = fmaf(fy, fy, accy);
    f2unpack(cz, plo, phi); float fz = plo - phi; accz = fmaf(fz, fz, accz);
}

// ---------------------------------------------------------------------------
// Scan: one thread = one row, pred+targ packed in f32x2 lanes.
// 64 blocks x 32 threads spread over 64 SMs.
// ---------------------------------------------------------------------------
__global__ void __launch_bounds__(32) scan_kernel(float* __restrict__ out)
{
    int row = blockIdx.x * 32 + threadIdx.x;     // 0..2047

    const ull SGN  = 0x8000000080000000ULL;
    const ull NEPS = f2pack(-EPSF, -EPSF);

    float4 iP = g_init[row];
    float4 iT = g_init[row + BROWS];

    // packed state: U = u1, V = u2 (roles alternate each step)
    ull Ux = f2pack(iP.x, iT.x), Uy = 0ULL, Uz = 0ULL;
    ull Vx = f2pack(iP.y, iT.y), Vy = f2pack(iP.z, iT.z), Vz = 0ULL;
    ull cx = f2pack(iP.x + iP.y, iT.x + iT.y);
    ull cy = f2pack(iP.z, iT.z);
    ull cz = 0ULL;

    float accx = 0.f, accy = 0.f, accz = 0.f;
    {   // atoms 1 and 2
        float d1 = iP.x - iT.x;
        float dx, dxh; f2unpack(cx, dx, dxh); float f2 = dx - dxh;
        float dy = iP.z - iT.z;
        accx = fmaf(d1, d1, accx);
        accx = fmaf(f2, f2, accx);
        accy = fmaf(dy, dy, accy);
    }

    const ulonglong2* __restrict__ p0 =
        reinterpret_cast<const ulonglong2*>(g_pk0) + row;
    const ull* __restrict__ p1 =
        reinterpret_cast<const ull*>(g_pk1) + row;

    ulonglong2 bxy[4]; ull bz[4];
#pragma unroll
    for (int u = 0; u < 4; ++u) {
        bxy[u] = __ldg(p0 + (size_t)u * RSTRIDE);
        bz[u]  = __ldg(p1 + (size_t)u * RSTRIDE);
    }

#pragma unroll 1
    for (int g = 0; g < 255; ++g) {              // steps 0..1019
        const ulonglong2* n0 = p0 + (size_t)4 * RSTRIDE;
        const ull*        n1 = p1 + (size_t)4 * RSTRIDE;

        ulonglong2 c0 = bxy[0]; ull z0 = bz[0];
        bxy[0] = __ldg(n0);              bz[0] = __ldg(n1);
        step_pk(c0.x, c0.y, z0, Ux, Uy, Uz, Vx, Vy, Vz, cx, cy, cz, NEPS, SGN, accx, accy, accz);

        ulonglong2 c1 = bxy[1]; ull z1 = bz[1];
        bxy[1] = __ldg(n0 + (size_t)RSTRIDE);   bz[1] = __ldg(n1 + (size_t)RSTRIDE);
        step_pk(c1.x, c1.y, z1, Vx, Vy, Vz, Ux, Uy, Uz, cx, cy, cz, NEPS, SGN, accx, accy, accz);

        ulonglong2 c2 = bxy[2]; ull z2 = bz[2];
        bxy[2] = __ldg(n0 + (size_t)2 * RSTRIDE); bz[2] = __ldg(n1 + (size_t)2 * RSTRIDE);
        step_pk(c2.x, c2.y, z2, Ux, Uy, Uz, Vx, Vy, Vz, cx, cy, cz, NEPS, SGN, accx, accy, accz);

        ulonglong2 c3 = bxy[3]; ull z3 = bz[3];
        bxy[3] = __ldg(n0 + (size_t)3 * RSTRIDE); bz[3] = __ldg(n1 + (size_t)3 * RSTRIDE);
        step_pk(c3.x, c3.y, z3, Vx, Vy, Vz, Ux, Uy, Uz, cx, cy, cz, NEPS, SGN, accx, accy, accz);

        p0 = n0; p1 = n1;
    }
    // step 1020 (ring slot 0 holds it after the last prefetch round)
    step_pk(bxy[0].x, bxy[0].y, bz[0], Ux, Uy, Uz, Vx, Vy, Vz, cx, cy, cz, NEPS, SGN, accx, accy, accz);

    float acc = accx + accy + accz;
#pragma unroll
    for (int off = 16; off > 0; off >>= 1)
        acc += __shfl_xor_sync(0xffffffffu, acc, off);

    if (threadIdx.x == 0) {
        atomicAdd(&g_acc, (double)acc);
        __threadfence();
        unsigned old = atomicAdd(&g_count, 1u);
        if (old == (unsigned)(gridDim.x - 1)) {
            double total;
            asm volatile("ld.global.cg.f64 %0, [%1];" : "=d"(total) : "l"(&g_acc));
            out[0] = (float)(total * (1.0 / (2048.0 * 1024.0 * 3.0)));
        }
    }
}

extern "C" void kernel_launch(void* const* d_in, const int* in_sizes, int n_in,
                              void* d_out, int out_size)
{
    const float* pred = (const float*)d_in[0];
    const float* targ = (const float*)d_in[1];
    float* out = (float*)d_out;

    dim3 pb(32, 32), pg(32, BROWS / 32);
    prep_kernel<<<pg, pb>>>(pred, targ);
    scan_kernel<<<BROWS / 32, 32>>>(out);
}

// round 12
// speedup vs baseline: 2.6452x; 2.6452x over previous
#include <cuda_runtime.h>
#include <cstdint>

#define LV     4087
#define BROWS  2048
#define NSTEP  1021
#define PSTEP  1024
#define EPSF   1e-6f

// Per (chain, step): A = {w'x, w'y, w'z, ct}, B = {st, cchi, schi, 0}
// Layout [chain][step], chains 0..2047 = pred, 2048..4095 = targ.  2 x 67MB.
__device__ float4 g_A[(size_t)2 * BROWS * PSTEP];
__device__ float4 g_B[(size_t)2 * BROWS * PSTEP];
__device__ float4 g_init[2 * BROWS];   // {l0, l1, ct0, st0}
__device__ double g_acc;
__device__ unsigned g_count;

__device__ __forceinline__ float dnbl(float v) { return ((v + 1.0f) * 0.5f) * 2.1f + 0.9f; }
__device__ __forceinline__ float dnd (float v) { return ((v + 1.0f) * 0.5f) * 3.5f + 1.5f; }
__device__ __forceinline__ float clip1(float v) { return fminf(fmaxf(v, -1.0f), 1.0f); }
__device__ __forceinline__ float clipE(float v) {
    return fminf(fmaxf(v, -1.0f + EPSF), 1.0f - EPSF);
}

// ---------------------------------------------------------------------------
// Prep: one thread per (row, step); computes pred AND targ params.
// w' carries the reference's eps column-deficits (s_bc, s_m, s_n) exactly.
// ---------------------------------------------------------------------------
__device__ __forceinline__ void prep_one(const float* __restrict__ v, int j, bool doClip,
                                         float4& A, float4& B,
                                         float& il0, float& il1, float& ictp, float& istp)
{
    float r_l0 = v[3064 + j];
    float r_l1 = v[3064 + j + 1];
    float r_l2 = v[3064 + j + 2];
    float r_d0 = v[2042 + j];
    float r_d1 = v[2042 + j + 1];
    float r_s0 = v[2 * j];
    float r_s1 = v[2 * j + 1];
    if (doClip) {
        r_l0 = clip1(r_l0); r_l1 = clip1(r_l1); r_l2 = clip1(r_l2);
        r_d0 = clip1(r_d0); r_d1 = clip1(r_d1);
        r_s0 = clip1(r_s0); r_s1 = clip1(r_s1);
    }
    float l0 = dnbl(r_l0), l1 = dnbl(r_l1), l2 = dnbl(r_l2);
    float d0 = dnd(r_d0), d1 = dnd(r_d1);

    // theta_prev: angle between bond(j+1), bond(j+2) — frame geometry
    float ctp = clipE((l0 * l0 + l1 * l1 - d0 * d0) / (2.0f * l0 * l1));
    float stp = sqrtf((1.0f - ctp) * (1.0f + ctp));
    // theta_cur: for the new bond
    float ctc = clipE((l1 * l1 + l2 * l2 - d1 * d1) / (2.0f * l1 * l2));
    float stc = sqrtf((1.0f - ctc) * (1.0f + ctc));

    float h2 = r_s0 * r_s0 + r_s1 * r_s1;
    float cch, sch;
    if (h2 < 1e-30f) { cch = 1.0f; sch = 0.0f; }
    else { float rh = rsqrtf(h2); cch = r_s1 * rh; sch = r_s0 * rh; }

    // eps column-deficit scales (reference: bc, n, m norms slightly < 1)
    float sbc = l1 / (l1 + EPSF);
    float cr  = l0 * sbc * stp;
    float sn  = cr / (cr + EPSF);
    float sm  = sn * sbc;

    A.x = -l2 * ctc * sbc;
    A.y =  l2 * stc * cch * sm;
    A.z =  l2 * stc * sch * sn;
    A.w = ctc;
    B.x = stc; B.y = cch; B.z = sch; B.w = 0.0f;

    il0 = l0; il1 = l1; ictp = ctp; istp = stp;
}

__global__ __launch_bounds__(256) void prep_kernel(const float* __restrict__ pred,
                                                   const float* __restrict__ targ)
{
    int j   = blockIdx.x * 256 + threadIdx.x;   // 0..1023
    int row = blockIdx.y;                        // 0..2047
    const float* vp = pred + (size_t)row * LV;
    const float* vt = targ + (size_t)row * LV;

    if (row == 0 && j == 0) { g_acc = 0.0; g_count = 0u; }

    float4 AP, BP, AT, BT;
    if (j < NSTEP) {
        float l0, l1, ctp, stp;
        prep_one(vp, j, true, AP, BP, l0, l1, ctp, stp);
        if (j == 0) g_init[row] = make_float4(l0, l1, ctp, stp);
        prep_one(vt, j, false, AT, BT, l0, l1, ctp, stp);
        if (j == 0) g_init[row + BROWS] = make_float4(l0, l1, ctp, stp);
    } else {
        AP = make_float4(0.f, 0.f, 0.f, -1.f);   // identity G, w = 0
        BP = make_float4(0.f, 1.f, 0.f, 0.f);
        AT = AP; BT = BP;
    }
    size_t ip = (size_t)row * PSTEP + j;
    size_t it = (size_t)(row + BROWS) * PSTEP + j;
    g_A[ip] = AP; g_B[ip] = BP;
    g_A[it] = AT; g_B[it] = BT;
}

// ---------------------------------------------------------------------------
// Affine algebra: R col-major (m[3c+r]); (L∘R) = (R_L·R_R, t_L + R_L·t_R)
// ---------------------------------------------------------------------------
struct Aff { float m[9]; float p[3]; };

__device__ __forceinline__ void mv(const float* m, float x, float y, float z, float* o)
{
    o[0] = fmaf(m[0], x, fmaf(m[3], y, m[6] * z));
    o[1] = fmaf(m[1], x, fmaf(m[4], y, m[7] * z));
    o[2] = fmaf(m[2], x, fmaf(m[5], y, m[8] * z));
}
__device__ __forceinline__ void matmul(const float* L, const float* G, float* O)
{
    mv(L, G[0], G[1], G[2], O + 0);
    mv(L, G[3], G[4], G[5], O + 3);
    mv(L, G[6], G[7], G[8], O + 6);
}
__device__ __forceinline__ void compose(const Aff& L, const Aff& R, Aff& O)
{
    matmul(L.m, R.m, O.m);
    float tv[3];
    mv(L.m, R.p[0], R.p[1], R.p[2], tv);
    O.p[0] = L.p[0] + tv[0];
    O.p[1] = L.p[1] + tv[1];
    O.p[2] = L.p[2] + tv[2];
}
__device__ __forceinline__ void buildG(const float4 A, const float4 B, Aff& G)
{
    float ct = A.w, st = B.x, cch = B.y, sch = B.z;
    G.m[0] = -ct;       G.m[1] = st * cch;  G.m[2] = st * sch;
    G.m[3] = -st;       G.m[4] = -ct * cch; G.m[5] = -ct * sch;
    G.m[6] = 0.f;       G.m[7] = -sch;      G.m[8] = cch;
    G.p[0] = A.x; G.p[1] = A.y; G.p[2] = A.z;
}
__device__ __forceinline__ void identityA(Aff& X)
{
    X.m[0] = 1.f; X.m[1] = 0.f; X.m[2] = 0.f;
    X.m[3] = 0.f; X.m[4] = 1.f; X.m[5] = 0.f;
    X.m[6] = 0.f; X.m[7] = 0.f; X.m[8] = 1.f;
    X.p[0] = X.p[1] = X.p[2] = 0.f;
}

// ---------------------------------------------------------------------------
// Scan: one block per row (pred + targ), 128 threads x 8 steps.
// Serial local compose -> 7-level Kogge-Stone (smem) -> apply + loss.
// ---------------------------------------------------------------------------
__global__ void __launch_bounds__(128) scan_kernel(float* __restrict__ out)
{
    __shared__ float sh[48][128];
    __shared__ float wred[4];
    const int t   = threadIdx.x;
    const int row = blockIdx.x;

    const float4* pAP = g_A + (size_t)row * PSTEP + 8 * t;
    const float4* pBP = g_B + (size_t)row * PSTEP + 8 * t;
    const float4* pAT = g_A + (size_t)(row + BROWS) * PSTEP + 8 * t;
    const float4* pBT = g_B + (size_t)(row + BROWS) * PSTEP + 8 * t;

    // ---- phase 1: serial local aggregate over 8 steps, both chains ----
    Aff incP, incT;
    {
        buildG(__ldg(pAP), __ldg(pBP), incP);
        buildG(__ldg(pAT), __ldg(pBT), incT);
#pragma unroll
        for (int jj = 1; jj < 8; ++jj) {
            Aff Gp, Gt, n;
            buildG(__ldg(pAP + jj), __ldg(pBP + jj), Gp);
            buildG(__ldg(pAT + jj), __ldg(pBT + jj), Gt);
            compose(incP, Gp, n); incP = n;
            compose(incT, Gt, n); incT = n;
        }
    }

    // ---- phase 2: Kogge-Stone inclusive scan over 128 aggregates ----
#pragma unroll
    for (int k = 0; k < 9; ++k) { sh[k][t] = incP.m[k];  sh[24 + k][t] = incT.m[k]; }
#pragma unroll
    for (int k = 0; k < 3; ++k) { sh[9 + k][t] = incP.p[k]; sh[33 + k][t] = incT.p[k]; }
    __syncthreads();

    for (int d = 1; d < 128; d <<= 1) {
        Aff oP, oT;
        int src = t - d;
        int s2  = src < 0 ? 0 : src;
#pragma unroll
        for (int k = 0; k < 9; ++k) { oP.m[k] = sh[k][s2];  oT.m[k] = sh[24 + k][s2]; }
#pragma unroll
        for (int k = 0; k < 3; ++k) { oP.p[k] = sh[9 + k][s2]; oT.p[k] = sh[33 + k][s2]; }
        __syncthreads();
        if (src >= 0) {
            Aff n;
            compose(oP, incP, n); incP = n;
            compose(oT, incT, n); incT = n;
        }
#pragma unroll
        for (int k = 0; k < 9; ++k) { sh[k][t] = incP.m[k];  sh[24 + k][t] = incT.m[k]; }
#pragma unroll
        for (int k = 0; k < 3; ++k) { sh[9 + k][t] = incP.p[k]; sh[33 + k][t] = incT.p[k]; }
        __syncthreads();
    }

    // ---- exclusive prefix ----
    Aff exP, exT;
    if (t == 0) { identityA(exP); identityA(exT); }
    else {
#pragma unroll
        for (int k = 0; k < 9; ++k) { exP.m[k] = sh[k][t - 1];  exT.m[k] = sh[24 + k][t - 1]; }
#pragma unroll
        for (int k = 0; k < 3; ++k) { exP.p[k] = sh[9 + k][t - 1]; exT.p[k] = sh[33 + k][t - 1]; }
    }

    // ---- globalize with initial frame S = (F2, p2) ----
    float4 iP = g_init[row];
    float4 iT = g_init[row + BROWS];
    Aff SP, ST;
    {   // F2 cols: bc=(-ct0,st0,0), m=(-st0,-ct0,0), n=(0,0,1); p2=(l0-l1*ct0, l1*st0, 0)
        float ct0 = iP.z, st0 = iP.w;
        SP.m[0] = -ct0; SP.m[1] = st0;  SP.m[2] = 0.f;
        SP.m[3] = -st0; SP.m[4] = -ct0; SP.m[5] = 0.f;
        SP.m[6] = 0.f;  SP.m[7] = 0.f;  SP.m[8] = 1.f;
        SP.p[0] = fmaf(-iP.y, ct0, iP.x); SP.p[1] = iP.y * st0; SP.p[2] = 0.f;
        float ct1 = iT.z, st1 = iT.w;
        ST.m[0] = -ct1; ST.m[1] = st1;  ST.m[2] = 0.f;
        ST.m[3] = -st1; ST.m[4] = -ct1; ST.m[5] = 0.f;
        ST.m[6] = 0.f;  ST.m[7] = 0.f;  ST.m[8] = 1.f;
        ST.p[0] = fmaf(-iT.y, ct1, iT.x); ST.p[1] = iT.y * st1; ST.p[2] = 0.f;
    }
    Aff RP, RT;
    compose(SP, exP, RP);
    compose(ST, exT, RT);

    // ---- phase 3: apply 8 steps, accumulate loss ----
    float acc = 0.f;
    if (t == 0) {   // atoms 1 and 2 (atom 0 identical zero)
        float d1 = iP.x - iT.x;
        float d2x = SP.p[0] - ST.p[0];
        float d2y = SP.p[1] - ST.p[1];
        acc = fmaf(d1, d1, fmaf(d2x, d2x, d2y * d2y));
    }
#pragma unroll
    for (int jj = 0; jj < 8; ++jj) {
        float4 aP = __ldg(pAP + jj), bP = __ldg(pBP + jj);
        float4 aT = __ldg(pAT + jj), bT = __ldg(pBT + jj);
        float e[3];
        mv(RP.m, aP.x, aP.y, aP.z, e);
        RP.p[0] += e[0]; RP.p[1] += e[1]; RP.p[2] += e[2];
        mv(RT.m, aT.x, aT.y, aT.z, e);
        RT.p[0] += e[0]; RT.p[1] += e[1]; RT.p[2] += e[2];

        if (8 * t + jj < NSTEP) {
            float fx = RP.p[0] - RT.p[0];
            float fy = RP.p[1] - RT.p[1];
            float fz = RP.p[2] - RT.p[2];
            acc = fmaf(fx, fx, acc);
            acc = fmaf(fy, fy, acc);
            acc = fmaf(fz, fz, acc);
        }
        if (jj < 7) {
            Aff G; float nm[9];
            buildG(aP, bP, G);
            matmul(RP.m, G.m, nm);
#pragma unroll
            for (int k = 0; k < 9; ++k) RP.m[k] = nm[k];
            buildG(aT, bT, G);
            matmul(RT.m, G.m, nm);
#pragma unroll
            for (int k = 0; k < 9; ++k) RT.m[k] = nm[k];
        }
    }

    // ---- block reduce + global accumulate ----
#pragma unroll
    for (int off = 16; off > 0; off >>= 1)
        acc += __shfl_xor_sync(0xffffffffu, acc, off);
    if ((t & 31) == 0) wred[t >> 5] = acc;
    __syncthreads();
    if (t == 0) {
        float tot = wred[0] + wred[1] + wred[2] + wred[3];
        atomicAdd(&g_acc, (double)tot);
        __threadfence();
        unsigned old = atomicAdd(&g_count, 1u);
        if (old == (unsigned)(gridDim.x - 1)) {
            double total;
            asm volatile("ld.global.cg.f64 %0, [%1];" : "=d"(total) : "l"(&g_acc));
            out[0] = (float)(total * (1.0 / (2048.0 * 1024.0 * 3.0)));
        }
    }
}

extern "C" void kernel_launch(void* const* d_in, const int* in_sizes, int n_in,
                              void* d_out, int out_size)
{
    const float* pred = (const float*)d_in[0];
    const float* targ = (const float*)d_in[1];
    float* out = (float*)d_out;

    dim3 pg(PSTEP / 256, BROWS);
    prep_kernel<<<pg, 256>>>(pred, targ);
    scan_kernel<<<BROWS, 128>>>(out);
}

// round 13
// speedup vs baseline: 3.5014x; 1.3237x over previous
#include <cuda_runtime.h>
#include <cstdint>

#define LV     4087
#define BROWS  2048
#define NSTEP  1021
#define PSTEP  1024
#define EPSF   1e-6f

// Permuted layout per chain: element for step j=8t+jj lives at [chain]*1024 + jj*128 + t
// A = {w'x, w'y, w'z, ct}, B = {st, cchi, schi, 0}.  2 x 67MB.
__device__ float4 g_A[(size_t)2 * BROWS * PSTEP];
__device__ float4 g_B[(size_t)2 * BROWS * PSTEP];
__device__ float4 g_init[2 * BROWS];   // {l0, l1, ct0, st0}
__device__ double g_acc;
__device__ unsigned g_count;

__device__ __forceinline__ float dnbl(float v) { return ((v + 1.0f) * 0.5f) * 2.1f + 0.9f; }
__device__ __forceinline__ float dnd (float v) { return ((v + 1.0f) * 0.5f) * 3.5f + 1.5f; }
__device__ __forceinline__ float clip1(float v) { return fminf(fmaxf(v, -1.0f), 1.0f); }
__device__ __forceinline__ float clipE(float v) {
    return fminf(fmaxf(v, -1.0f + EPSF), 1.0f - EPSF);
}

// ---------------------------------------------------------------------------
// Per-step parameters (identical math to R12; w' carries the eps deficits).
// ---------------------------------------------------------------------------
__device__ __forceinline__ void prep_one(const float* __restrict__ v, int j, bool doClip,
                                         float4& A, float4& B,
                                         float& il0, float& il1, float& ictp, float& istp)
{
    float r_l0 = v[3064 + j];
    float r_l1 = v[3064 + j + 1];
    float r_l2 = v[3064 + j + 2];
    float r_d0 = v[2042 + j];
    float r_d1 = v[2042 + j + 1];
    float r_s0 = v[2 * j];
    float r_s1 = v[2 * j + 1];
    if (doClip) {
        r_l0 = clip1(r_l0); r_l1 = clip1(r_l1); r_l2 = clip1(r_l2);
        r_d0 = clip1(r_d0); r_d1 = clip1(r_d1);
        r_s0 = clip1(r_s0); r_s1 = clip1(r_s1);
    }
    float l0 = dnbl(r_l0), l1 = dnbl(r_l1), l2 = dnbl(r_l2);
    float d0 = dnd(r_d0), d1 = dnd(r_d1);

    float ctp = clipE((l0 * l0 + l1 * l1 - d0 * d0) / (2.0f * l0 * l1));
    float stp = sqrtf((1.0f - ctp) * (1.0f + ctp));
    float ctc = clipE((l1 * l1 + l2 * l2 - d1 * d1) / (2.0f * l1 * l2));
    float stc = sqrtf((1.0f - ctc) * (1.0f + ctc));

    float h2 = r_s0 * r_s0 + r_s1 * r_s1;
    float cch, sch;
    if (h2 < 1e-30f) { cch = 1.0f; sch = 0.0f; }
    else { float rh = rsqrtf(h2); cch = r_s1 * rh; sch = r_s0 * rh; }

    float sbc = l1 / (l1 + EPSF);
    float cr  = l0 * sbc * stp;
    float sn  = cr / (cr + EPSF);
    float sm  = sn * sbc;

    A.x = -l2 * ctc * sbc;
    A.y =  l2 * stc * cch * sm;
    A.z =  l2 * stc * sch * sn;
    A.w = ctc;
    B.x = stc; B.y = cch; B.z = sch; B.w = 0.0f;

    il0 = l0; il1 = l1; ictp = ctp; istp = stp;
}

// ---------------------------------------------------------------------------
// Prep: block = (j-tile of 256) x row. Computes both chains, then emits the
// PERMUTED layout via padded smem so scan loads are coalesced.
// smem pad: local j -> 9*(j>>3) + (j&7)  (stride-9 kills the 128B-stride conflict)
// ---------------------------------------------------------------------------
__global__ __launch_bounds__(256) void prep_kernel(const float* __restrict__ pred,
                                                   const float* __restrict__ targ)
{
    __shared__ float4 sAP[288], sBP[288], sAT[288], sBT[288];
    const int tid = threadIdx.x;
    const int J0  = blockIdx.x * 256;
    const int row = blockIdx.y;
    const int j   = J0 + tid;
    const float* vp = pred + (size_t)row * LV;
    const float* vt = targ + (size_t)row * LV;

    if (row == 0 && j == 0) { g_acc = 0.0; g_count = 0u; }

    float4 AP, BP, AT, BT;
    if (j < NSTEP) {
        float l0, l1, ctp, stp;
        prep_one(vp, j, true, AP, BP, l0, l1, ctp, stp);
        if (j == 0) g_init[row] = make_float4(l0, l1, ctp, stp);
        prep_one(vt, j, false, AT, BT, l0, l1, ctp, stp);
        if (j == 0) g_init[row + BROWS] = make_float4(l0, l1, ctp, stp);
    } else {
        AP = make_float4(0.f, 0.f, 0.f, -1.f);   // identity G, w = 0
        BP = make_float4(0.f, 1.f, 0.f, 0.f);
        AT = AP; BT = BP;
    }
    int ip = 9 * (tid >> 3) + (tid & 7);
    sAP[ip] = AP; sBP[ip] = BP; sAT[ip] = AT; sBT[ip] = BT;
    __syncthreads();

    // write phase: warp w -> jj = w, lanes -> consecutive t (coalesced stores)
    const int jj   = tid >> 5;
    const int lane = tid & 31;
    const int T0   = blockIdx.x * 32;            // 32 t-values per j-tile
    int src = 9 * lane + jj;
    size_t dstP = (size_t)row * PSTEP + jj * 128 + T0 + lane;
    size_t dstT = (size_t)(row + BROWS) * PSTEP + jj * 128 + T0 + lane;
    g_A[dstP] = sAP[src]; g_B[dstP] = sBP[src];
    g_A[dstT] = sAT[src]; g_B[dstT] = sBT[src];
}

// ---------------------------------------------------------------------------
// Affine algebra (col-major m[3c+r]); (L∘R) = (R_L·R_R, t_L + R_L·t_R)
// ---------------------------------------------------------------------------
struct Aff { float m[9]; float p[3]; };

__device__ __forceinline__ void mv(const float* m, float x, float y, float z, float* o)
{
    o[0] = fmaf(m[0], x, fmaf(m[3], y, m[6] * z));
    o[1] = fmaf(m[1], x, fmaf(m[4], y, m[7] * z));
    o[2] = fmaf(m[2], x, fmaf(m[5], y, m[8] * z));
}
__device__ __forceinline__ void matmul(const float* L, const float* G, float* O)
{
    mv(L, G[0], G[1], G[2], O + 0);
    mv(L, G[3], G[4], G[5], O + 3);
    mv(L, G[6], G[7], G[8], O + 6);
}
__device__ __forceinline__ void compose(const Aff& L, const Aff& R, Aff& O)
{
    matmul(L.m, R.m, O.m);
    float tv[3];
    mv(L.m, R.p[0], R.p[1], R.p[2], tv);
    O.p[0] = L.p[0] + tv[0];
    O.p[1] = L.p[1] + tv[1];
    O.p[2] = L.p[2] + tv[2];
}
__device__ __forceinline__ void buildG(const float4 A, const float4 B, Aff& G)
{
    float ct = A.w, st = B.x, cch = B.y, sch = B.z;
    G.m[0] = -ct;       G.m[1] = st * cch;  G.m[2] = st * sch;
    G.m[3] = -st;       G.m[4] = -ct * cch; G.m[5] = -ct * sch;
    G.m[6] = 0.f;       G.m[7] = -sch;      G.m[8] = cch;
    G.p[0] = A.x; G.p[1] = A.y; G.p[2] = A.z;
}
__device__ __forceinline__ void identityA(Aff& X)
{
    X.m[0] = 1.f; X.m[1] = 0.f; X.m[2] = 0.f;
    X.m[3] = 0.f; X.m[4] = 1.f; X.m[5] = 0.f;
    X.m[6] = 0.f; X.m[7] = 0.f; X.m[8] = 1.f;
    X.p[0] = X.p[1] = X.p[2] = 0.f;
}

// ---------------------------------------------------------------------------
// Scan: one block per row (pred+targ), 128 threads x 8 steps.
// Phase 1: coalesced loads, serial compose, stash local prefix translations.
// Phase 2: Kogge-Stone (smem). Phase 3: pos = R.p + R.m*pl (R constant!).
// ---------------------------------------------------------------------------
__global__ void __launch_bounds__(128) scan_kernel(float* __restrict__ out)
{
    __shared__ float sh[48][128];   // KS scan state
    __shared__ float pl[48][128];   // local prefix translations, P: 0..23, T: 24..47
    __shared__ float wred[4];
    const int t   = threadIdx.x;
    const int row = blockIdx.x;

    const float4* AP = g_A + (size_t)row * PSTEP + t;
    const float4* BP = g_B + (size_t)row * PSTEP + t;
    const float4* AT = g_A + (size_t)(row + BROWS) * PSTEP + t;
    const float4* BT = g_B + (size_t)(row + BROWS) * PSTEP + t;

    // ---- phase 1: coalesced loads, serial aggregate, stash prefix p ----
    Aff incP, incT;
#pragma unroll
    for (int jj = 0; jj < 8; ++jj) {
        float4 aP = __ldg(AP + jj * 128), bP = __ldg(BP + jj * 128);
        float4 aT = __ldg(AT + jj * 128), bT = __ldg(BT + jj * 128);
        if (jj == 0) {
            buildG(aP, bP, incP);
            buildG(aT, bT, incT);
        } else {
            Aff G, n;
            buildG(aP, bP, G); compose(incP, G, n); incP = n;
            buildG(aT, bT, G); compose(incT, G, n); incT = n;
        }
        pl[jj * 3 + 0][t] = incP.p[0];
        pl[jj * 3 + 1][t] = incP.p[1];
        pl[jj * 3 + 2][t] = incP.p[2];
        pl[24 + jj * 3 + 0][t] = incT.p[0];
        pl[24 + jj * 3 + 1][t] = incT.p[1];
        pl[24 + jj * 3 + 2][t] = incT.p[2];
    }

    // ---- phase 2: Kogge-Stone inclusive scan over 128 aggregates ----
#pragma unroll
    for (int k = 0; k < 9; ++k) { sh[k][t] = incP.m[k];  sh[24 + k][t] = incT.m[k]; }
#pragma unroll
    for (int k = 0; k < 3; ++k) { sh[9 + k][t] = incP.p[k]; sh[33 + k][t] = incT.p[k]; }
    __syncthreads();

    for (int d = 1; d < 128; d <<= 1) {
        Aff oP, oT;
        int src = t - d;
        int s2  = src < 0 ? 0 : src;
#pragma unroll
        for (int k = 0; k < 9; ++k) { oP.m[k] = sh[k][s2];  oT.m[k] = sh[24 + k][s2]; }
#pragma unroll
        for (int k = 0; k < 3; ++k) { oP.p[k] = sh[9 + k][s2]; oT.p[k] = sh[33 + k][s2]; }
        __syncthreads();
        if (src >= 0) {
            Aff n;
            compose(oP, incP, n); incP = n;
            compose(oT, incT, n); incT = n;
        }
#pragma unroll
        for (int k = 0; k < 9; ++k) { sh[k][t] = incP.m[k];  sh[24 + k][t] = incT.m[k]; }
#pragma unroll
        for (int k = 0; k < 3; ++k) { sh[9 + k][t] = incP.p[k]; sh[33 + k][t] = incT.p[k]; }
        __syncthreads();
    }

    // ---- exclusive prefix ----
    Aff exP, exT;
    if (t == 0) { identityA(exP); identityA(exT); }
    else {
#pragma unroll
        for (int k = 0; k < 9; ++k) { exP.m[k] = sh[k][t - 1];  exT.m[k] = sh[24 + k][t - 1]; }
#pragma unroll
        for (int k = 0; k < 3; ++k) { exP.p[k] = sh[9 + k][t - 1]; exT.p[k] = sh[33 + k][t - 1]; }
    }

    // ---- globalize with initial frame S = (F2, p2) ----
    float4 iP = g_init[row];
    float4 iT = g_init[row + BROWS];
    Aff SP, ST;
    {
        float ct0 = iP.z, st0 = iP.w;
        SP.m[0] = -ct0; SP.m[1] = st0;  SP.m[2] = 0.f;
        SP.m[3] = -st0; SP.m[4] = -ct0; SP.m[5] = 0.f;
        SP.m[6] = 0.f;  SP.m[7] = 0.f;  SP.m[8] = 1.f;
        SP.p[0] = fmaf(-iP.y, ct0, iP.x); SP.p[1] = iP.y * st0; SP.p[2] = 0.f;
        float ct1 = iT.z, st1 = iT.w;
        ST.m[0] = -ct1; ST.m[1] = st1;  ST.m[2] = 0.f;
        ST.m[3] = -st1; ST.m[4] = -ct1; ST.m[5] = 0.f;
        ST.m[6] = 0.f;  ST.m[7] = 0.f;  ST.m[8] = 1.f;
        ST.p[0] = fmaf(-iT.y, ct1, iT.x); ST.p[1] = iT.y * st1; ST.p[2] = 0.f;
    }
    Aff RP, RT;
    compose(SP, exP, RP);
    compose(ST, exT, RT);

    // ---- phase 3: positions from stashed local translations (R constant) ----
    float acc = 0.f;
    if (t == 0) {
        float d1 = iP.x - iT.x;
        float d2x = SP.p[0] - ST.p[0];
        float d2y = SP.p[1] - ST.p[1];
        acc = fmaf(d1, d1, fmaf(d2x, d2x, d2y * d2y));
    }
#pragma unroll
    for (int jj = 0; jj < 8; ++jj) {
        if (8 * t + jj < NSTEP) {
            float lx = pl[jj * 3 + 0][t], ly = pl[jj * 3 + 1][t], lz = pl[jj * 3 + 2][t];
            float e[3];
            mv(RP.m, lx, ly, lz, e);
            float px = RP.p[0] + e[0], py = RP.p[1] + e[1], pz = RP.p[2] + e[2];
            lx = pl[24 + jj * 3 + 0][t]; ly = pl[24 + jj * 3 + 1][t]; lz = pl[24 + jj * 3 + 2][t];
            mv(RT.m, lx, ly, lz, e);
            float fx = px - (RT.p[0] + e[0]);
            float fy = py - (RT.p[1] + e[1]);
            float fz = pz - (RT.p[2] + e[2]);
            acc = fmaf(fx, fx, acc);
            acc = fmaf(fy, fy, acc);
            acc = fmaf(fz, fz, acc);
        }
    }

    // ---- block reduce + global accumulate ----
#pragma unroll
    for (int off = 16; off > 0; off >>= 1)
        acc += __shfl_xor_sync(0xffffffffu, acc, off);
    if ((t & 31) == 0) wred[t >> 5] = acc;
    __syncthreads();
    if (t == 0) {
        float tot = wred[0] + wred[1] + wred[2] + wred[3];
        atomicAdd(&g_acc, (double)tot);
        __threadfence();
        unsigned old = atomicAdd(&g_count, 1u);
        if (old == (unsigned)(gridDim.x - 1)) {
            double total;
            asm volatile("ld.global.cg.f64 %0, [%1];" : "=d"(total) : "l"(&g_acc));
            out[0] = (float)(total * (1.0 / (2048.0 * 1024.0 * 3.0)));
        }
    }
}

extern "C" void kernel_launch(void* const* d_in, const int* in_sizes, int n_in,
                              void* d_out, int out_size)
{
    const float* pred = (const float*)d_in[0];
    const float* targ = (const float*)d_in[1];
    float* out = (float*)d_out;

    dim3 pg(PSTEP / 256, BROWS);
    prep_kernel<<<pg, 256>>>(pred, targ);
    scan_kernel<<<BROWS, 128>>>(out);
}

// round 14
// speedup vs baseline: 5.9606x; 1.7023x over previous
#include <cuda_runtime.h>
#include <cstdint>

#define LV     4087
#define BROWS  2048
#define NSTEP  1021
#define EPSF   1e-6f

__device__ double   g_acc   = 0.0;
__device__ unsigned g_count = 0u;

__device__ __forceinline__ float dnbl(float v) { return ((v + 1.0f) * 0.5f) * 2.1f + 0.9f; }
__device__ __forceinline__ float dnd (float v) { return ((v + 1.0f) * 0.5f) * 3.5f + 1.5f; }
__device__ __forceinline__ float clip1(float v) { return fminf(fmaxf(v, -1.0f), 1.0f); }
__device__ __forceinline__ float clipE(float v) { return fminf(fmaxf(v, -1.0f + EPSF), 1.0f - EPSF); }
__device__ __forceinline__ float rcp_a(float x){ float y; asm("rcp.approx.f32 %0,%1;":"=f"(y):"f"(x)); return y; }
__device__ __forceinline__ float rsq_a(float x){ float y; asm("rsqrt.approx.f32 %0,%1;":"=f"(y):"f"(x)); return y; }
__device__ __forceinline__ float sqt_a(float x){ float y; asm("sqrt.approx.f32 %0,%1;":"=f"(y):"f"(x)); return y; }

// ---------------------------------------------------------------------------
// Affine algebra (col-major m[3c+r]); (L∘R) = (R_L·R_R, t_L + R_L·t_R)
// ---------------------------------------------------------------------------
struct Aff { float m[9]; float p[3]; };

__device__ __forceinline__ void mv(const float* m, float x, float y, float z, float* o)
{
    o[0] = fmaf(m[0], x, fmaf(m[3], y, m[6] * z));
    o[1] = fmaf(m[1], x, fmaf(m[4], y, m[7] * z));
    o[2] = fmaf(m[2], x, fmaf(m[5], y, m[8] * z));
}
__device__ __forceinline__ void compose(const Aff& L, const Aff& R, Aff& O)
{
    mv(L.m, R.m[0], R.m[1], R.m[2], O.m + 0);
    mv(L.m, R.m[3], R.m[4], R.m[5], O.m + 3);
    mv(L.m, R.m[6], R.m[7], R.m[8], O.m + 6);
    float tv[3];
    mv(L.m, R.p[0], R.p[1], R.p[2], tv);
    O.p[0] = L.p[0] + tv[0];
    O.p[1] = L.p[1] + tv[1];
    O.p[2] = L.p[2] + tv[2];
}
__device__ __forceinline__ void identityA(Aff& X)
{
    X.m[0] = 1.f; X.m[1] = 0.f; X.m[2] = 0.f;
    X.m[3] = 0.f; X.m[4] = 1.f; X.m[5] = 0.f;
    X.m[6] = 0.f; X.m[7] = 0.f; X.m[8] = 1.f;
    X.p[0] = X.p[1] = X.p[2] = 0.f;
}

// ---------------------------------------------------------------------------
// Shared-memory layout (dynamic):
//   pl      [48*128]       local prefix translations (P rows 0..23, T 24..47)
//   uni     [2*4620]       staging (stP | stT)  -- ALIASED by KS array sh[48*128]
//   ish     [8]            init params {l0,l1,ct0,st0} x {P,T}
//   wred    [4]
// Staged index padding kills bank conflicts for the stride-8/16 reads.
// ---------------------------------------------------------------------------
#define SPAD(a)  ((a) + ((a) >> 3))
#define STG_F    4620
#define PL_F     (48 * 128)
#define UNI_F    (2 * STG_F)
#define ISH_OFF  (PL_F + UNI_F)
#define WRED_OFF (ISH_OFF + 8)
#define SMEM_F   (WRED_OFF + 4)
#define SMEM_BYTES (SMEM_F * 4)

// ---------------------------------------------------------------------------
// Phase 1 for one chain: coefficients from staged input (approx math, sliding
// angle window), build G, serial-compose 8 steps, stash prefix translations.
// Identical formulation to R12/R13 (w' carries the reference eps deficits).
// ---------------------------------------------------------------------------
__device__ __forceinline__ void chain_phase1(const float* __restrict__ st, int t,
                                             float* __restrict__ plc, Aff& inc,
                                             float* __restrict__ ish_slot)
{
    const int j0 = 8 * t;
    float l_a = dnbl(st[SPAD(3064 + j0)]);
    float l_b = dnbl(st[SPAD(3064 + j0 + 1)]);
    float d_a = dnd (st[SPAD(2042 + j0)]);
    float ctp = clipE((l_a * l_a + l_b * l_b - d_a * d_a) * rcp_a(2.0f * l_a * l_b));
    float stp = sqt_a((1.0f - ctp) * (1.0f + ctp));
    if (t == 0) {
        ish_slot[0] = l_a; ish_slot[1] = l_b; ish_slot[2] = ctp; ish_slot[3] = stp;
    }
#pragma unroll
    for (int jj = 0; jj < 8; ++jj) {
        const int j = j0 + jj;
        float l_c = dnbl(st[SPAD(3064 + j + 2)]);
        float d_b = dnd (st[SPAD(2042 + j + 1)]);
        float ctc = clipE((l_b * l_b + l_c * l_c - d_b * d_b) * rcp_a(2.0f * l_b * l_c));
        float stc = sqt_a((1.0f - ctc) * (1.0f + ctc));

        float s0 = st[SPAD(2 * j)];
        float s1 = st[SPAD(2 * j + 1)];
        float h2 = s0 * s0 + s1 * s1;
        float cch, sch;
        if (h2 < 1e-30f) { cch = 1.0f; sch = 0.0f; }
        else { float rh = rsq_a(h2); cch = s1 * rh; sch = s0 * rh; }

        float sbc = l_b * rcp_a(l_b + EPSF);
        float cr  = l_a * sbc * stp;
        float sn  = cr * rcp_a(cr + EPSF);
        float sm  = sn * sbc;

        float wx = -l_c * ctc * sbc;
        float wy =  l_c * stc * cch * sm;
        float wz =  l_c * stc * sch * sn;
        if (j >= NSTEP) { ctc = -1.f; stc = 0.f; cch = 1.f; sch = 0.f; wx = wy = wz = 0.f; }

        Aff G;
        G.m[0] = -ctc;      G.m[1] = stc * cch;  G.m[2] = stc * sch;
        G.m[3] = -stc;      G.m[4] = -ctc * cch; G.m[5] = -ctc * sch;
        G.m[6] = 0.f;       G.m[7] = -sch;       G.m[8] = cch;
        G.p[0] = wx; G.p[1] = wy; G.p[2] = wz;

        if (jj == 0) inc = G;
        else { Aff n; compose(inc, G, n); inc = n; }

        plc[(jj * 3 + 0) * 128 + t] = inc.p[0];
        plc[(jj * 3 + 1) * 128 + t] = inc.p[1];
        plc[(jj * 3 + 2) * 128 + t] = inc.p[2];

        l_a = l_b; l_b = l_c; ctp = ctc; stp = stc;
    }
}

// ---------------------------------------------------------------------------
// Fused kernel: one block per row. Stage inputs -> coefficients in-register ->
// KS scan -> loss. No scratch DRAM traffic at all.
// ---------------------------------------------------------------------------
__global__ void __launch_bounds__(128) fused_kernel(const float* __restrict__ pred,
                                                    const float* __restrict__ targ,
                                                    float* __restrict__ out)
{
    extern __shared__ float smem[];
    float* pl   = smem;
    float* uni  = smem + PL_F;
    float* stP  = uni;
    float* stT  = uni + STG_F;
    float* sh   = uni;                 // aliases staging (used after phase 1)
    float* ish  = smem + ISH_OFF;
    float* wred = smem + WRED_OFF;

    const int t   = threadIdx.x;
    const int row = blockIdx.x;
    const float* vp = pred + (size_t)row * LV;
    const float* vt = targ + (size_t)row * LV;

    // ---- stage inputs (coalesced); pred clipped at stage time ----
    for (int i = t; i < 4104; i += 128) {
        float a = (i < LV) ? clip1(__ldg(vp + i)) : 0.f;
        float b = (i < LV) ? __ldg(vt + i) : 0.f;
        stP[SPAD(i)] = a;
        stT[SPAD(i)] = b;
    }
    __syncthreads();

    // ---- phase 1: both chains ----
    Aff incP, incT;
    chain_phase1(stP, t, pl,             incP, ish);
    chain_phase1(stT, t, pl + 24 * 128,  incT, ish + 4);
    __syncthreads();   // all staging reads done -> sh may now alias it

    // ---- phase 2: Kogge-Stone over 128 aggregates ----
#pragma unroll
    for (int k = 0; k < 9; ++k) { sh[k * 128 + t] = incP.m[k];  sh[(24 + k) * 128 + t] = incT.m[k]; }
#pragma unroll
    for (int k = 0; k < 3; ++k) { sh[(9 + k) * 128 + t] = incP.p[k]; sh[(33 + k) * 128 + t] = incT.p[k]; }
    __syncthreads();

    for (int d = 1; d < 128; d <<= 1) {
        Aff oP, oT;
        int src = t - d;
        int s2  = src < 0 ? 0 : src;
#pragma unroll
        for (int k = 0; k < 9; ++k) { oP.m[k] = sh[k * 128 + s2];  oT.m[k] = sh[(24 + k) * 128 + s2]; }
#pragma unroll
        for (int k = 0; k < 3; ++k) { oP.p[k] = sh[(9 + k) * 128 + s2]; oT.p[k] = sh[(33 + k) * 128 + s2]; }
        __syncthreads();
        if (src >= 0) {
            Aff n;
            compose(oP, incP, n); incP = n;
            compose(oT, incT, n); incT = n;
        }
#pragma unroll
        for (int k = 0; k < 9; ++k) { sh[k * 128 + t] = incP.m[k];  sh[(24 + k) * 128 + t] = incT.m[k]; }
#pragma unroll
        for (int k = 0; k < 3; ++k) { sh[(9 + k) * 128 + t] = incP.p[k]; sh[(33 + k) * 128 + t] = incT.p[k]; }
        __syncthreads();
    }

    // ---- exclusive prefix ----
    Aff exP, exT;
    if (t == 0) { identityA(exP); identityA(exT); }
    else {
#pragma unroll
        for (int k = 0; k < 9; ++k) { exP.m[k] = sh[k * 128 + t - 1];  exT.m[k] = sh[(24 + k) * 128 + t - 1]; }
#pragma unroll
        for (int k = 0; k < 3; ++k) { exP.p[k] = sh[(9 + k) * 128 + t - 1]; exT.p[k] = sh[(33 + k) * 128 + t - 1]; }
    }

    // ---- globalize with initial frame S = (F2, p2) ----
    float l0P = ish[0], l1P = ish[1], ct0 = ish[2], st0 = ish[3];
    float l0T = ish[4], l1T = ish[5], ct1 = ish[6], st1 = ish[7];
    Aff SP, ST;
    SP.m[0] = -ct0; SP.m[1] = st0;  SP.m[2] = 0.f;
    SP.m[3] = -st0; SP.m[4] = -ct0; SP.m[5] = 0.f;
    SP.m[6] = 0.f;  SP.m[7] = 0.f;  SP.m[8] = 1.f;
    SP.p[0] = fmaf(-l1P, ct0, l0P); SP.p[1] = l1P * st0; SP.p[2] = 0.f;
    ST.m[0] = -ct1; ST.m[1] = st1;  ST.m[2] = 0.f;
    ST.m[3] = -st1; ST.m[4] = -ct1; ST.m[5] = 0.f;
    ST.m[6] = 0.f;  ST.m[7] = 0.f;  ST.m[8] = 1.f;
    ST.p[0] = fmaf(-l1T, ct1, l0T); ST.p[1] = l1T * st1; ST.p[2] = 0.f;

    Aff RP, RT;
    compose(SP, exP, RP);
    compose(ST, exT, RT);

    // ---- phase 3: positions from stashed local translations (R constant) ----
    float acc = 0.f;
    if (t == 0) {
        float d1  = l0P - l0T;
        float d2x = SP.p[0] - ST.p[0];
        float d2y = SP.p[1] - ST.p[1];
        acc = fmaf(d1, d1, fmaf(d2x, d2x, d2y * d2y));
    }
#pragma unroll
    for (int jj = 0; jj < 8; ++jj) {
        if (8 * t + jj < NSTEP) {
            float lx = pl[(jj * 3 + 0) * 128 + t];
            float ly = pl[(jj * 3 + 1) * 128 + t];
            float lz = pl[(jj * 3 + 2) * 128 + t];
            float e[3];
            mv(RP.m, lx, ly, lz, e);
            float px = RP.p[0] + e[0], py = RP.p[1] + e[1], pz = RP.p[2] + e[2];
            lx = pl[(24 + jj * 3 + 0) * 128 + t];
            ly = pl[(24 + jj * 3 + 1) * 128 + t];
            lz = pl[(24 + jj * 3 + 2) * 128 + t];
            mv(RT.m, lx, ly, lz, e);
            float fx = px - (RT.p[0] + e[0]);
            float fy = py - (RT.p[1] + e[1]);
            float fz = pz - (RT.p[2] + e[2]);
            acc = fmaf(fx, fx, acc);
            acc = fmaf(fy, fy, acc);
            acc = fmaf(fz, fz, acc);
        }
    }

    // ---- reduce + global accumulate; last block finalizes and self-resets ----
#pragma unroll
    for (int off = 16; off > 0; off >>= 1)
        acc += __shfl_xor_sync(0xffffffffu, acc, off);
    if ((t & 31) == 0) wred[t >> 5] = acc;
    __syncthreads();
    if (t == 0) {
        float tot = wred[0] + wred[1] + wred[2] + wred[3];
        atomicAdd(&g_acc, (double)tot);
        __threadfence();
        unsigned old = atomicAdd(&g_count, 1u);
        if (old == (unsigned)(gridDim.x - 1)) {
            double total;
            asm volatile("ld.global.cg.f64 %0, [%1];" : "=d"(total) : "l"(&g_acc));
            out[0] = (float)(total * (1.0 / (2048.0 * 1024.0 * 3.0)));
            // self-reset for the next graph replay (all blocks are done here)
            asm volatile("st.global.cg.f64 [%0], %1;" :: "l"(&g_acc), "d"(0.0));
            __threadfence();
            asm volatile("st.global.cg.u32 [%0], %1;" :: "l"(&g_count), "r"(0u));
        }
    }
}

extern "C" void kernel_launch(void* const* d_in, const int* in_sizes, int n_in,
                              void* d_out, int out_size)
{
    const float* pred = (const float*)d_in[0];
    const float* targ = (const float*)d_in[1];
    float* out = (float*)d_out;

    cudaFuncSetAttribute(fused_kernel,
                         cudaFuncAttributeMaxDynamicSharedMemorySize, SMEM_BYTES);
    fused_kernel<<<BROWS, 128, SMEM_BYTES>>>(pred, targ, out);
}